// round 5
// baseline (speedup 1.0000x reference)
#include <cuda_runtime.h>
#include <cstdint>

#define BB 2
#define LL 2048
#define HH 16
#define EE 64
#define NKT 32

// Frag-ready preprocessed operands (tf32-rounded):
//  g_Qp[bh][l][pd], g_Kp[bh][l][pd]  with pd = frag-permuted dim
//  g_Vt[bh][d][pk]                   with pk = frag-permuted key (transposed V)
__device__ float g_Qp[BB * HH * LL * EE];
__device__ float g_Kp[BB * HH * LL * EE];
__device__ float g_Vt[BB * HH * EE * LL];

#define LOG2E 1.4426950408889634f
#define SCL2  0.18033688011112042592f   // 0.125 * log2(e)

__device__ __forceinline__ uint32_t f2tf(float x) {
    uint32_t u;
    asm("cvt.rna.tf32.f32 %0, %1;" : "=r"(u) : "f"(x));
    return u;
}
__device__ __forceinline__ float tfr(float x) { return __uint_as_float(f2tf(x)); }
__device__ __forceinline__ float ex2f(float x) {
    float o;
    asm("ex2.approx.f32 %0, %1;" : "=f"(o) : "f"(x));
    return o;
}
__device__ __forceinline__ void mma8(float c[4], const uint32_t a[4],
                                     uint32_t b0, uint32_t b1) {
    asm volatile(
        "mma.sync.aligned.m16n8k8.row.col.f32.tf32.tf32.f32 "
        "{%0,%1,%2,%3}, {%4,%5,%6,%7}, {%8,%9}, {%0,%1,%2,%3};"
        : "+f"(c[0]), "+f"(c[1]), "+f"(c[2]), "+f"(c[3])
        : "r"(a[0]), "r"(a[1]), "r"(a[2]), "r"(a[3]), "r"(b0), "r"(b1));
}

// frag permutation: d = kb*8 + u*4 + t  ->  (kb>>1)*16 + t*4 + (kb&1)*2 + u
__device__ __forceinline__ int permd(int d) {
    return ((d >> 4) << 4) + (d & 3) * 4 + ((d >> 3) & 1) * 2 + ((d >> 2) & 1);
}

// ---------------------------------------------------------------------------
// Prepass 1: RoPE + permute + tf32-round Q,K into [bh][l][pd] layout.
// ---------------------------------------------------------------------------
__global__ void rope_perm_kernel(const float* __restrict__ q,
                                 const float* __restrict__ k) {
    int idx = blockIdx.x * blockDim.x + threadIdx.x;
    const int N4 = BB * LL * HH * 16;
    if (idx >= N4) return;
    int e4  = idx & 15;
    int row = idx >> 4;
    int h = row & 15;
    int bl = row >> 4;
    int l = bl & (LL - 1);
    int b = bl >> 11;
    float4 vq = ((const float4*)q)[idx];
    float4 vk = ((const float4*)k)[idx];
    if (e4 < 8) {
        float i0 = (float)(e4 * 2);
        const float NEG_L2 = -0.83048202372184058696f;  // -log2(10000)/16
        float s0, c0, s1, c1;
        sincosf((float)l * exp2f(i0 * NEG_L2), &s0, &c0);
        sincosf((float)l * exp2f((i0 + 1.0f) * NEG_L2), &s1, &c1);
        float4 o;
        o.x = c0 * vq.x - s0 * vq.y;  o.y = c0 * vq.y + s0 * vq.x;
        o.z = c1 * vq.z - s1 * vq.w;  o.w = c1 * vq.w + s1 * vq.z;
        vq = o;
        o.x = c0 * vk.x - s0 * vk.y;  o.y = c0 * vk.y + s0 * vk.x;
        o.z = c1 * vk.z - s1 * vk.w;  o.w = c1 * vk.w + s1 * vk.z;
        vk = o;
    }
    int e = e4 * 4;
    int p0 = permd(e);
    size_t base = ((size_t)(b * HH + h) * LL + l) * EE;
    float* qd = g_Qp + base;
    float* kd = g_Kp + base;
    qd[p0] = tfr(vq.x); qd[p0 + 4] = tfr(vq.y); qd[p0 + 8] = tfr(vq.z); qd[p0 + 12] = tfr(vq.w);
    kd[p0] = tfr(vk.x); kd[p0 + 4] = tfr(vk.y); kd[p0 + 8] = tfr(vk.z); kd[p0 + 12] = tfr(vk.w);
}

// ---------------------------------------------------------------------------
// Prepass 2: transpose V per (b,h,kt) tile -> g_Vt[bh][d][kt*64 + pk(j)]
// ---------------------------------------------------------------------------
__global__ void vt_kernel(const float* __restrict__ v) {
    __shared__ float vs[64 * 65];
    const int kt = blockIdx.x, h = blockIdx.y, b = blockIdx.z;
    const int tid = threadIdx.x;
    const float* Vg = v + ((size_t)(b * LL + kt * 64) * HH + h) * EE;
    #pragma unroll
    for (int it = 0; it < 4; it++) {
        int i = it * 256 + tid;
        int j = i >> 4, e = (i & 15) * 4;
        float4 w = *(const float4*)(Vg + (size_t)j * (HH * EE) + e);
        vs[j * 65 + e + 0] = w.x; vs[j * 65 + e + 1] = w.y;
        vs[j * 65 + e + 2] = w.z; vs[j * 65 + e + 3] = w.w;
    }
    __syncthreads();
    float* Vd = g_Vt + (size_t)(b * HH + h) * EE * LL + kt * 64;
    #pragma unroll
    for (int it = 0; it < 16; it++) {
        int i = it * 256 + tid;
        int d = i >> 6, j = i & 63;
        Vd[(size_t)d * LL + permd(j)] = tfr(vs[j * 65 + d]);
    }
}

// ---------------------------------------------------------------------------
// Main attention, depth-paired tiles.
// CTA = 128 query rows = 2 variables (A: rows 0-63, B: rows 64-127).
// Warp w processes tiles of depth d in {w, 7-w}; tile(d) = 16-row mma tile
// whose low half is var-A group d (rows 8d..8d+7) and high half is var-B
// group d (rows 64+8d..64+8d+7). Both halves share mask depth d, so the
// tile needs exactly d+1 key blocks -> 9 blocks/warp/kt, balanced.
// Q frags reloaded from L1 each kt (saves 64 regs); O stays in regs.
// ---------------------------------------------------------------------------
__global__ __launch_bounds__(128, 3)
void attn3(const float* __restrict__ bw, float* __restrict__ out) {
    const int tid  = threadIdx.x;
    const int lane = tid & 31;
    const int w    = tid >> 5;
    const int g    = lane >> 2;
    const int t    = lane & 3;
    const int qtb  = blockIdx.x;
    const int h    = blockIdx.y;
    const int b    = blockIdx.z;
    const int bh   = b * HH + h;
    const int l0   = qtb * 128;

    const int dep[2] = { w, 7 - w };

    const float b2s = bw[HH + h] * LOG2E;
    const float b2d = bw[h] * LOG2E;

    float oacc[2][8][4];
    #pragma unroll
    for (int ti = 0; ti < 2; ti++)
        #pragma unroll
        for (int db = 0; db < 8; db++)
            #pragma unroll
            for (int i = 0; i < 4; i++) oacc[ti][db][i] = 0.0f;
    float lsum[2][2] = {{0.0f, 0.0f}, {0.0f, 0.0f}};

    const int  src0 = (lane & ~3) + (t >> 1);
    const int  src1 = src0 + 2;
    const bool odd  = (t & 1);

    const float* Qp  = g_Qp + ((size_t)bh * LL + l0) * EE;
    const float* Kp0 = g_Kp + (size_t)bh * LL * EE;
    const float* Vt0 = g_Vt + (size_t)bh * EE * LL;

    for (int kt = 0; kt < NKT; kt++) {
        const float* Kt = Kp0 + (size_t)kt * 64 * EE;
        const float* Vt = Vt0 + kt * 64;
        const float biasA = (kt == 2 * qtb)     ? b2s : b2d;   // var A (low half)
        const float biasB = (kt == 2 * qtb + 1) ? b2s : b2d;   // var B (high half)

        #pragma unroll
        for (int ti = 0; ti < 2; ti++) {
            const int d  = dep[ti];
            const int rA = 8 * d + g;          // local row (var A); var B = rA+64
            const int n0 = rA;                 // mask threshold (both halves)

            // ---- Q A-frags for this tile (L1-hit reload) ----
            uint32_t qa[8][4];
            #pragma unroll
            for (int kbp = 0; kbp < 4; kbp++) {
                uint4 x = *(const uint4*)(Qp + (size_t)rA * EE + kbp * 16 + t * 4);
                uint4 y = *(const uint4*)(Qp + (size_t)(rA + 64) * EE + kbp * 16 + t * 4);
                qa[2 * kbp][0] = x.x;  qa[2 * kbp][2] = x.y;
                qa[2 * kbp + 1][0] = x.z;  qa[2 * kbp + 1][2] = x.w;
                qa[2 * kbp][1] = y.x;  qa[2 * kbp][3] = y.y;
                qa[2 * kbp + 1][1] = y.z;  qa[2 * kbp + 1][3] = y.w;
            }

            for (int nb = 0; nb <= d; nb++) {
                // ---- K frags ----
                uint4 kq[4];
                #pragma unroll
                for (int kbp = 0; kbp < 4; kbp++)
                    kq[kbp] = *(const uint4*)(Kt + (size_t)(nb * 8 + g) * EE + kbp * 16 + t * 4);

                // ---- S = Q K^T (two parallel 4-mma chains) ----
                float cE[4] = {0, 0, 0, 0}, cO[4] = {0, 0, 0, 0};
                #pragma unroll
                for (int kbp = 0; kbp < 4; kbp++) {
                    mma8(cE, qa[2 * kbp],     kq[kbp].x, kq[kbp].y);
                    mma8(cO, qa[2 * kbp + 1], kq[kbp].z, kq[kbp].w);
                }
                const float c0 = cE[0] + cO[0], c1 = cE[1] + cO[1];
                const float c2 = cE[2] + cO[2], c3 = cE[3] + cO[3];

                // ---- softmax (no max-subtract) + mask ----
                const int c0i = nb * 8 + 2 * t, c1i = c0i + 1;
                float p0 = (c0i <= n0) ? ex2f(fmaf(c0, SCL2, biasA)) : 0.0f;
                float p1 = (c1i <= n0) ? ex2f(fmaf(c1, SCL2, biasA)) : 0.0f;
                float p2 = (c0i <= n0) ? ex2f(fmaf(c2, SCL2, biasB)) : 0.0f;
                float p3 = (c1i <= n0) ? ex2f(fmaf(c3, SCL2, biasB)) : 0.0f;
                lsum[ti][0] += p0 + p1;
                lsum[ti][1] += p2 + p3;

                // ---- P C-frag -> A-frag relayout (quad shuffles) ----
                uint32_t pa[4];
                uint32_t u0 = f2tf(p0), u1 = f2tf(p1), u2 = f2tf(p2), u3 = f2tf(p3);
                uint32_t x0 = __shfl_sync(0xffffffffu, u0, src0);
                uint32_t x1 = __shfl_sync(0xffffffffu, u1, src0);
                pa[0] = odd ? x1 : x0;
                uint32_t y0 = __shfl_sync(0xffffffffu, u2, src0);
                uint32_t y1 = __shfl_sync(0xffffffffu, u3, src0);
                pa[1] = odd ? y1 : y0;
                uint32_t z0 = __shfl_sync(0xffffffffu, u0, src1);
                uint32_t z1 = __shfl_sync(0xffffffffu, u1, src1);
                pa[2] = odd ? z1 : z0;
                uint32_t w0 = __shfl_sync(0xffffffffu, u2, src1);
                uint32_t w1 = __shfl_sync(0xffffffffu, u3, src1);
                pa[3] = odd ? w1 : w0;

                // ---- O += P V ----
                const float* Vb = Vt + (nb >> 1) * 16 + (nb & 1) * 2 + t * 4;
                #pragma unroll
                for (int db = 0; db < 8; db++) {
                    uint2 vb = *(const uint2*)(Vb + (size_t)(db * 8 + g) * LL);
                    mma8(oacc[ti][db], pa, vb.x, vb.y);
                }
            }
        }
    }

    // ---- reduce row sums across quad, normalize, store ----
    #pragma unroll
    for (int ti = 0; ti < 2; ti++)
        #pragma unroll
        for (int i = 0; i < 2; i++) {
            float v = lsum[ti][i];
            v += __shfl_xor_sync(0xffffffffu, v, 1);
            v += __shfl_xor_sync(0xffffffffu, v, 2);
            lsum[ti][i] = 1.0f / v;
        }

    #pragma unroll
    for (int ti = 0; ti < 2; ti++) {
        const int d  = dep[ti];
        const int rA = l0 + 8 * d + g;        // var A row
        const int rB = rA + 64;               // var B row
        #pragma unroll
        for (int db = 0; db < 8; db++) {
            float2 v0;
            v0.x = oacc[ti][db][0] * lsum[ti][0];
            v0.y = oacc[ti][db][1] * lsum[ti][0];
            *(float2*)(out + (((size_t)(b * LL + rA)) * HH + h) * EE + db * 8 + 2 * t) = v0;
            float2 v1;
            v1.x = oacc[ti][db][2] * lsum[ti][1];
            v1.y = oacc[ti][db][3] * lsum[ti][1];
            *(float2*)(out + (((size_t)(b * LL + rB)) * HH + h) * EE + db * 8 + 2 * t) = v1;
        }
    }
}

// ---------------------------------------------------------------------------
extern "C" void kernel_launch(void* const* d_in, const int* in_sizes, int n_in,
                              void* d_out, int out_size) {
    const float* q  = (const float*)d_in[0];
    const float* k  = (const float*)d_in[1];
    const float* v  = (const float*)d_in[2];
    const float* bw = (const float*)d_in[3];
    float* out = (float*)d_out;

    const int N4 = BB * LL * HH * 16;
    rope_perm_kernel<<<(N4 + 255) / 256, 256>>>(q, k);
    vt_kernel<<<dim3(NKT, HH, BB), 256>>>(v);

    dim3 grid(LL / 128, HH, BB);
    attn3<<<grid, 128>>>(bw, out);
}

// round 6
// speedup vs baseline: 1.4336x; 1.4336x over previous
#include <cuda_runtime.h>
#include <cstdint>

#define BB 2
#define LL 2048
#define HH 16
#define EE 64
#define NKT 32

// Frag-ready preprocessed operands (tf32-rounded):
//  g_Qp[bh][l][pd], g_Kp[bh][l][pd]  with pd = frag-permuted dim
//  g_Vt[bh][d][pk]                   with pk = frag-permuted key (transposed V)
__device__ float g_Qp[BB * HH * LL * EE];
__device__ float g_Kp[BB * HH * LL * EE];
__device__ float g_Vt[BB * HH * EE * LL];

#define LOG2E 1.4426950408889634f
#define SCL2  0.18033688011112042592f   // 0.125 * log2(e)

__device__ __forceinline__ uint32_t f2tf(float x) {
    uint32_t u;
    asm("cvt.rna.tf32.f32 %0, %1;" : "=r"(u) : "f"(x));
    return u;
}
__device__ __forceinline__ float tfr(float x) { return __uint_as_float(f2tf(x)); }
__device__ __forceinline__ float ex2f(float x) {
    float o;
    asm("ex2.approx.f32 %0, %1;" : "=f"(o) : "f"(x));
    return o;
}
__device__ __forceinline__ void mma8(float c[4], const uint32_t a[4],
                                     uint32_t b0, uint32_t b1) {
    asm volatile(
        "mma.sync.aligned.m16n8k8.row.col.f32.tf32.tf32.f32 "
        "{%0,%1,%2,%3}, {%4,%5,%6,%7}, {%8,%9}, {%0,%1,%2,%3};"
        : "+f"(c[0]), "+f"(c[1]), "+f"(c[2]), "+f"(c[3])
        : "r"(a[0]), "r"(a[1]), "r"(a[2]), "r"(a[3]), "r"(b0), "r"(b1));
}

// frag permutation: d = kb*8 + u*4 + t  ->  (kb>>1)*16 + t*4 + (kb&1)*2 + u
__device__ __forceinline__ int permd(int d) {
    return ((d >> 4) << 4) + (d & 3) * 4 + ((d >> 3) & 1) * 2 + ((d >> 2) & 1);
}

// ---------------------------------------------------------------------------
// Prepass 1: RoPE + permute + tf32-round Q,K into [bh][l][pd] layout.
// ---------------------------------------------------------------------------
__global__ void rope_perm_kernel(const float* __restrict__ q,
                                 const float* __restrict__ k) {
    int idx = blockIdx.x * blockDim.x + threadIdx.x;
    const int N4 = BB * LL * HH * 16;
    if (idx >= N4) return;
    int e4  = idx & 15;
    int row = idx >> 4;
    int h = row & 15;
    int bl = row >> 4;
    int l = bl & (LL - 1);
    int b = bl >> 11;
    float4 vq = ((const float4*)q)[idx];
    float4 vk = ((const float4*)k)[idx];
    if (e4 < 8) {
        float i0 = (float)(e4 * 2);
        const float NEG_L2 = -0.83048202372184058696f;  // -log2(10000)/16
        float s0, c0, s1, c1;
        sincosf((float)l * exp2f(i0 * NEG_L2), &s0, &c0);
        sincosf((float)l * exp2f((i0 + 1.0f) * NEG_L2), &s1, &c1);
        float4 o;
        o.x = c0 * vq.x - s0 * vq.y;  o.y = c0 * vq.y + s0 * vq.x;
        o.z = c1 * vq.z - s1 * vq.w;  o.w = c1 * vq.w + s1 * vq.z;
        vq = o;
        o.x = c0 * vk.x - s0 * vk.y;  o.y = c0 * vk.y + s0 * vk.x;
        o.z = c1 * vk.z - s1 * vk.w;  o.w = c1 * vk.w + s1 * vk.z;
        vk = o;
    }
    int e = e4 * 4;
    int p0 = permd(e);
    size_t base = ((size_t)(b * HH + h) * LL + l) * EE;
    float* qd = g_Qp + base;
    float* kd = g_Kp + base;
    qd[p0] = tfr(vq.x); qd[p0 + 4] = tfr(vq.y); qd[p0 + 8] = tfr(vq.z); qd[p0 + 12] = tfr(vq.w);
    kd[p0] = tfr(vk.x); kd[p0 + 4] = tfr(vk.y); kd[p0 + 8] = tfr(vk.z); kd[p0 + 12] = tfr(vk.w);
}

// ---------------------------------------------------------------------------
// Prepass 2: transpose V per (b,h,kt) tile -> g_Vt[bh][d][kt*64 + pk(j)]
// ---------------------------------------------------------------------------
__global__ void vt_kernel(const float* __restrict__ v) {
    __shared__ float vs[64 * 65];
    const int kt = blockIdx.x, h = blockIdx.y, b = blockIdx.z;
    const int tid = threadIdx.x;
    const float* Vg = v + ((size_t)(b * LL + kt * 64) * HH + h) * EE;
    #pragma unroll
    for (int it = 0; it < 4; it++) {
        int i = it * 256 + tid;
        int j = i >> 4, e = (i & 15) * 4;
        float4 w = *(const float4*)(Vg + (size_t)j * (HH * EE) + e);
        vs[j * 65 + e + 0] = w.x; vs[j * 65 + e + 1] = w.y;
        vs[j * 65 + e + 2] = w.z; vs[j * 65 + e + 3] = w.w;
    }
    __syncthreads();
    float* Vd = g_Vt + (size_t)(b * HH + h) * EE * LL + kt * 64;
    #pragma unroll
    for (int it = 0; it < 16; it++) {
        int i = it * 256 + tid;
        int d = i >> 6, j = i & 63;
        Vd[(size_t)d * LL + permd(j)] = tfr(vs[j * 65 + d]);
    }
}

// ---------------------------------------------------------------------------
// Main attention. 256 threads = 8 warps per CTA; CTA = 128 query rows
// (variables A: rows 0-63, B: rows 64-127).
// Warp w owns the depth-w paired tile: low half = var-A group w (rows
// 8w..8w+7), high half = var-B group w (rows 64+8w..64+8w+7). Both halves
// have mask threshold 8w+g, so exactly w+1 key blocks are needed (exact
// triangle, 36 blocks/CTA/kt). nbp loop statically unrolled with a
// warp-uniform continue so LDGs stay batched (R5 lesson).
// ---------------------------------------------------------------------------
__global__ __launch_bounds__(256, 2)
void attn4(const float* __restrict__ bw, float* __restrict__ out) {
    const int tid  = threadIdx.x;
    const int lane = tid & 31;
    const int w    = tid >> 5;       // warp = tile depth, 0..7
    const int g    = lane >> 2;
    const int t    = lane & 3;
    const int qtb  = blockIdx.x;
    const int h    = blockIdx.y;
    const int b    = blockIdx.z;
    const int bh   = b * HH + h;
    const int l0   = qtb * 128;

    const float b2s = bw[HH + h] * LOG2E;
    const float b2d = bw[h] * LOG2E;

    const int rA = 8 * w + g;        // var-A local row; var-B row = rA + 64
    const int n0 = rA;               // mask threshold (both halves)

    // ---- persistent Q A-frags: a0,a2 = var A row; a1,a3 = var B row ----
    const float* Qp = g_Qp + ((size_t)bh * LL + l0) * EE;
    uint32_t qa[8][4];
    #pragma unroll
    for (int kbp = 0; kbp < 4; kbp++) {
        uint4 x = *(const uint4*)(Qp + (size_t)rA * EE + kbp * 16 + t * 4);
        uint4 y = *(const uint4*)(Qp + (size_t)(rA + 64) * EE + kbp * 16 + t * 4);
        qa[2 * kbp][0] = x.x;      qa[2 * kbp][2] = x.y;
        qa[2 * kbp + 1][0] = x.z;  qa[2 * kbp + 1][2] = x.w;
        qa[2 * kbp][1] = y.x;      qa[2 * kbp][3] = y.y;
        qa[2 * kbp + 1][1] = y.z;  qa[2 * kbp + 1][3] = y.w;
    }

    float oacc[8][4];
    #pragma unroll
    for (int db = 0; db < 8; db++)
        #pragma unroll
        for (int i = 0; i < 4; i++) oacc[db][i] = 0.0f;
    float lsA = 0.0f, lsB = 0.0f;

    const int  src0 = (lane & ~3) + (t >> 1);
    const int  src1 = src0 + 2;
    const bool odd  = (t & 1);

    const float* Kp0 = g_Kp + (size_t)bh * LL * EE;
    const float* Vt0 = g_Vt + (size_t)bh * EE * LL;

    for (int kt = 0; kt < NKT; kt++) {
        const float* Kt = Kp0 + (size_t)kt * 64 * EE;
        const float* Vt = Vt0 + kt * 64;
        const float biasA = (kt == 2 * qtb)     ? b2s : b2d;
        const float biasB = (kt == 2 * qtb + 1) ? b2s : b2d;

        #pragma unroll
        for (int nbp = 0; nbp < 4; nbp++) {
            const int nb0 = 2 * nbp, nb1 = nb0 + 1;
            if (nb0 > w) continue;              // warp-uniform prune
            const bool a1 = (nb1 <= w);

            // ---- K frags (batched LDG.128) ----
            uint4 kq0[4], kq1[4];
            #pragma unroll
            for (int kbp = 0; kbp < 4; kbp++)
                kq0[kbp] = *(const uint4*)(Kt + (size_t)(nb0 * 8 + g) * EE + kbp * 16 + t * 4);
            if (a1) {
                #pragma unroll
                for (int kbp = 0; kbp < 4; kbp++)
                    kq1[kbp] = *(const uint4*)(Kt + (size_t)(nb1 * 8 + g) * EE + kbp * 16 + t * 4);
            }

            // ---- S = Q K^T (two independent 8-mma chains) ----
            float c0[4] = {0, 0, 0, 0}, c1[4] = {0, 0, 0, 0};
            #pragma unroll
            for (int kbp = 0; kbp < 4; kbp++) {
                mma8(c0, qa[2 * kbp],     kq0[kbp].x, kq0[kbp].y);
                if (a1) mma8(c1, qa[2 * kbp],     kq1[kbp].x, kq1[kbp].y);
                mma8(c0, qa[2 * kbp + 1], kq0[kbp].z, kq0[kbp].w);
                if (a1) mma8(c1, qa[2 * kbp + 1], kq1[kbp].z, kq1[kbp].w);
            }

            // ---- softmax + P frag relayout (quad shuffles) ----
            uint32_t pa0[4], pa1[4];
            #pragma unroll
            for (int nbi = 0; nbi < 2; nbi++) {
                if (nbi && !a1) continue;
                float* c = nbi ? c1 : c0;
                const int ci = (nb0 + nbi) * 8 + 2 * t;
                float p0 = (ci     <= n0) ? ex2f(fmaf(c[0], SCL2, biasA)) : 0.0f;
                float p1 = (ci + 1 <= n0) ? ex2f(fmaf(c[1], SCL2, biasA)) : 0.0f;
                float p2 = (ci     <= n0) ? ex2f(fmaf(c[2], SCL2, biasB)) : 0.0f;
                float p3 = (ci + 1 <= n0) ? ex2f(fmaf(c[3], SCL2, biasB)) : 0.0f;
                lsA += p0 + p1;
                lsB += p2 + p3;
                uint32_t* pa = nbi ? pa1 : pa0;
                uint32_t u0 = f2tf(p0), u1 = f2tf(p1), u2 = f2tf(p2), u3 = f2tf(p3);
                uint32_t x0 = __shfl_sync(0xffffffffu, u0, src0);
                uint32_t x1 = __shfl_sync(0xffffffffu, u1, src0);
                pa[0] = odd ? x1 : x0;
                uint32_t y0 = __shfl_sync(0xffffffffu, u2, src0);
                uint32_t y1 = __shfl_sync(0xffffffffu, u3, src0);
                pa[1] = odd ? y1 : y0;
                uint32_t z0 = __shfl_sync(0xffffffffu, u0, src1);
                uint32_t z1 = __shfl_sync(0xffffffffu, u1, src1);
                pa[2] = odd ? z1 : z0;
                uint32_t w0 = __shfl_sync(0xffffffffu, u2, src1);
                uint32_t w1 = __shfl_sync(0xffffffffu, u3, src1);
                pa[3] = odd ? w1 : w0;
            }

            // ---- O += P V (uint4 covers b-frags for nb0 and nb1) ----
            const float* Vb = Vt + nbp * 16 + t * 4;
            #pragma unroll
            for (int db = 0; db < 8; db++) {
                uint4 vq = *(const uint4*)(Vb + (size_t)(db * 8 + g) * LL);
                mma8(oacc[db], pa0, vq.x, vq.y);
                if (a1) mma8(oacc[db], pa1, vq.z, vq.w);
            }
        }
    }

    // ---- reduce row sums across quad, normalize, store ----
    lsA += __shfl_xor_sync(0xffffffffu, lsA, 1);
    lsA += __shfl_xor_sync(0xffffffffu, lsA, 2);
    lsB += __shfl_xor_sync(0xffffffffu, lsB, 1);
    lsB += __shfl_xor_sync(0xffffffffu, lsB, 2);
    const float invA = 1.0f / lsA;
    const float invB = 1.0f / lsB;

    const int rowA = l0 + rA;
    const int rowB = rowA + 64;
    #pragma unroll
    for (int db = 0; db < 8; db++) {
        float2 v0;
        v0.x = oacc[db][0] * invA;
        v0.y = oacc[db][1] * invA;
        *(float2*)(out + (((size_t)(b * LL + rowA)) * HH + h) * EE + db * 8 + 2 * t) = v0;
        float2 v1;
        v1.x = oacc[db][2] * invB;
        v1.y = oacc[db][3] * invB;
        *(float2*)(out + (((size_t)(b * LL + rowB)) * HH + h) * EE + db * 8 + 2 * t) = v1;
    }
}

// ---------------------------------------------------------------------------
extern "C" void kernel_launch(void* const* d_in, const int* in_sizes, int n_in,
                              void* d_out, int out_size) {
    const float* q  = (const float*)d_in[0];
    const float* k  = (const float*)d_in[1];
    const float* v  = (const float*)d_in[2];
    const float* bw = (const float*)d_in[3];
    float* out = (float*)d_out;

    const int N4 = BB * LL * HH * 16;
    rope_perm_kernel<<<(N4 + 255) / 256, 256>>>(q, k);
    vt_kernel<<<dim3(NKT, HH, BB), 256>>>(v);

    dim3 grid(LL / 128, HH, BB);
    attn4<<<grid, 256>>>(bw, out);
}